// round 6
// baseline (speedup 1.0000x reference)
#include <cuda_runtime.h>
#include <math.h>

// Model dims
#define NB      16      // batch rows per block
#define NTH     512     // threads: 2 groups x 256 hidden units
#define RPT     8       // rows per thread (NB / 2 groups)
#define HD      256     // hidden
#define TV      64      // vocab
#define TSTEPS  119     // T-1

typedef unsigned long long u64;

// ---------------- device-global scratch --------------------------------------
__device__ float4 g_whT[3][64 * 768];   // w_hh layers 0..2, [k4][768] float4
__device__ float4 g_wiT[2][64 * 768];   // w_ih layers 1..2
__device__ float4 g_owT[64 * 64];       // out_w [k4][64] float4
__device__ float  g_table[64 * 768];    // emb @ w_ih0^T + b_ih0

// ---------------- packed f32x2 helpers ---------------------------------------
__device__ __forceinline__ void unpack2(u64 v, float& lo, float& hi) {
    asm("mov.b64 {%0, %1}, %2;" : "=f"(lo), "=f"(hi) : "l"(v));
}
__device__ __forceinline__ void fma2(u64& a, u64 b, u64 c) {
    asm("fma.rn.f32x2 %0, %1, %2, %0;" : "+l"(a) : "l"(b), "l"(c));
}
__device__ __forceinline__ float hsum2(u64 v) {
    float lo, hi; unpack2(v, lo, hi); return lo + hi;
}

// ---------------- accurate activations ---------------------------------------
__device__ __forceinline__ float sigf(float x) { return 1.0f / (1.0f + expf(-x)); }
__device__ __forceinline__ float tanh_acc(float x) {
    float ax = fabsf(x);
    float e  = expf(-2.0f * ax);
    float t  = (1.0f - e) / (1.0f + e);
    return (x >= 0.0f) ? t : -t;
}

// ---------------- prep --------------------------------------------------------
__global__ void prep_kernel(const float* __restrict__ w_hh0,
                            const float* __restrict__ w_hh1,
                            const float* __restrict__ w_hh2,
                            const float* __restrict__ w_ih1,
                            const float* __restrict__ w_ih2,
                            const float* __restrict__ out_w,
                            const float* __restrict__ emb,
                            const float* __restrict__ w_ih0,
                            const float* __restrict__ b_ih0)
{
    int idx    = blockIdx.x * blockDim.x + threadIdx.x;
    int stride = gridDim.x * blockDim.x;

    for (int e = idx; e < 768 * 256; e += stride) {
        int row = e >> 8;
        int k   = e & 255;
        int di  = (k >> 2) * 768 + row;
        int kk  = k & 3;
        ((float*)&g_whT[0][di])[kk] = w_hh0[e];
        ((float*)&g_whT[1][di])[kk] = w_hh1[e];
        ((float*)&g_whT[2][di])[kk] = w_hh2[e];
        ((float*)&g_wiT[0][di])[kk] = w_ih1[e];
        ((float*)&g_wiT[1][di])[kk] = w_ih2[e];
    }
    for (int e = idx; e < 64 * 256; e += stride) {
        int v = e >> 8;
        int k = e & 255;
        ((float*)&g_owT[(k >> 2) * 64 + v])[k & 3] = out_w[e];
    }
    for (int e = idx; e < 64 * 768; e += stride) {
        int v  = e / 768;
        int jj = e - v * 768;
        const float* er = emb   + v  * 64;
        const float* wr = w_ih0 + jj * 64;
        float acc = b_ih0[jj];
        #pragma unroll 8
        for (int t = 0; t < 64; ++t) acc = fmaf(er[t], wr[t], acc);
        g_table[e] = acc;
    }
}

// k-packed triple-stream GEMM: a{0,1,2}[bb] += w{r,z,n} . x[bb]
// Weights reinterpreted as ulonglong2 (two k-pairs per float4) -> zero movs.
// Accumulator lanes hold (even-k partial, odd-k partial); hsum at epilogue.
__device__ __forceinline__ void gemm3k(const ulonglong2* __restrict__ w2,
                                       const float*  __restrict__ xb,
                                       int j, u64* a0, u64* a1, u64* a2)
{
    #pragma unroll 4
    for (int k4 = 0; k4 < 64; ++k4) {
        ulonglong2 wr = w2[k4 * 768 + j];
        ulonglong2 wz = w2[k4 * 768 + j + 256];
        ulonglong2 wn = w2[k4 * 768 + j + 512];
        const float* xk = xb + k4 * 4;
        #pragma unroll
        for (int bb = 0; bb < RPT; ++bb) {
            ulonglong2 xv = *reinterpret_cast<const ulonglong2*>(xk + bb * HD);
            fma2(a0[bb], wr.x, xv.x); fma2(a0[bb], wr.y, xv.y);
            fma2(a1[bb], wz.x, xv.x); fma2(a1[bb], wz.y, xv.y);
            fma2(a2[bb], wn.x, xv.x); fma2(a2[bb], wn.y, xv.y);
        }
    }
}

// ---------------- main persistent decoder ------------------------------------
__global__ void __launch_bounds__(NTH, 1)
decoder_kernel(const float* __restrict__ z,
               const float* __restrict__ z2h_w,
               const float* __restrict__ z2h_b,
               const float* __restrict__ b_hh0,
               const float* __restrict__ b_ih1, const float* __restrict__ b_hh1,
               const float* __restrict__ b_ih2, const float* __restrict__ b_hh2,
               const float* __restrict__ out_b,
               float* __restrict__ out)
{
    extern __shared__ float smem[];
    float* hbuf = smem;                         // [3][NB][HD] row-major
    float* slog = smem + 3 * NB * HD;           // [NB][TV]
    int*   stok = (int*)(slog + NB * TV);       // [NB]

    const int tid = threadIdx.x;
    const int b0  = blockIdx.x * NB;
    const int j   = tid & 255;                  // hidden unit
    const int g   = tid >> 8;                   // row group 0/1 (8 rows each)

    // ---- init h0 = tanh(z @ z2h_w^T + z2h_b); tokens = 1
    for (int idx = tid; idx < NB * 768; idx += NTH) {
        int b = idx / 768;
        int u = idx - b * 768;                  // u = l*256 + jj
        const float* wr = z2h_w + u * 128;
        const float* zr = z + (size_t)(b0 + b) * 128;
        float acc = z2h_b[u];
        #pragma unroll 8
        for (int k = 0; k < 128; ++k) acc = fmaf(wr[k], zr[k], acc);
        int l  = u >> 8;
        int jj = u & 255;
        hbuf[(l * NB + b) * HD + jj] = tanh_acc(acc);
    }
    if (tid < NB) stok[tid] = 1;
    __syncthreads();

    // ---- hoisted per-thread constants
    const float c0r = b_hh0[j], c0z = b_hh0[j + 256], c0n = b_hh0[j + 512];
    const float c1r = b_ih1[j] + b_hh1[j];
    const float c1z = b_ih1[j + 256] + b_hh1[j + 256];
    const float c1i = b_ih1[j + 512];
    const float c1h = b_hh1[j + 512];
    const float c2r = b_ih2[j] + b_hh2[j];
    const float c2z = b_ih2[j + 256] + b_hh2[j + 256];
    const float c2i = b_ih2[j + 512];
    const float c2h = b_hh2[j + 512];
    const int   vv  = tid & 63;
    const int   rg  = tid >> 6;                 // 0..7 -> 2 rows each for logits
    const float ob  = out_b[vv];

    const ulonglong2* wh0 = reinterpret_cast<const ulonglong2*>(g_whT[0]);
    const ulonglong2* wh1 = reinterpret_cast<const ulonglong2*>(g_whT[1]);
    const ulonglong2* wh2 = reinterpret_cast<const ulonglong2*>(g_whT[2]);
    const ulonglong2* wi1 = reinterpret_cast<const ulonglong2*>(g_wiT[0]);
    const ulonglong2* wi2 = reinterpret_cast<const ulonglong2*>(g_wiT[1]);
    const ulonglong2* ow2 = reinterpret_cast<const ulonglong2*>(g_owT);

    float* hb0 = hbuf + (0 * NB + g * RPT) * HD;
    float* hb1 = hbuf + (1 * NB + g * RPT) * HD;
    float* hb2 = hbuf + (2 * NB + g * RPT) * HD;

    u64 ar[RPT], az[RPT], ai[RPT], ah[RPT];
    float hnew[RPT];

    for (int t = 0; t < TSTEPS; ++t) {
        // ================= layer 0 (input side = token table) ================
        #pragma unroll
        for (int bb = 0; bb < RPT; ++bb) { ar[bb] = 0ULL; az[bb] = 0ULL; ah[bb] = 0ULL; }
        gemm3k(wh0, hb0, j, ar, az, ah);
        #pragma unroll
        for (int bb = 0; bb < RPT; ++bb) {
            const float* trow = g_table + stok[g * RPT + bb] * 768;
            float r  = sigf(hsum2(ar[bb]) + trow[j] + c0r);
            float u  = sigf(hsum2(az[bb]) + trow[j + 256] + c0z);
            float n  = tanh_acc(fmaf(r, hsum2(ah[bb]) + c0n, trow[j + 512]));
            float ho = hb0[bb * HD + j];
            hnew[bb] = (1.0f - u) * n + u * ho;
        }
        __syncthreads();
        #pragma unroll
        for (int bb = 0; bb < RPT; ++bb) hb0[bb * HD + j] = hnew[bb];
        __syncthreads();

        // ================= layer 1 ==========================================
        #pragma unroll
        for (int bb = 0; bb < RPT; ++bb) { ar[bb] = 0ULL; az[bb] = 0ULL; ai[bb] = 0ULL; ah[bb] = 0ULL; }
        gemm3k(wi1, hb0, j, ar, az, ai);
        gemm3k(wh1, hb1, j, ar, az, ah);
        #pragma unroll
        for (int bb = 0; bb < RPT; ++bb) {
            float r  = sigf(hsum2(ar[bb]) + c1r);
            float u  = sigf(hsum2(az[bb]) + c1z);
            float n  = tanh_acc(fmaf(r, hsum2(ah[bb]) + c1h, hsum2(ai[bb]) + c1i));
            float ho = hb1[bb * HD + j];
            hnew[bb] = (1.0f - u) * n + u * ho;
        }
        __syncthreads();
        #pragma unroll
        for (int bb = 0; bb < RPT; ++bb) hb1[bb * HD + j] = hnew[bb];
        __syncthreads();

        // ================= layer 2 ==========================================
        #pragma unroll
        for (int bb = 0; bb < RPT; ++bb) { ar[bb] = 0ULL; az[bb] = 0ULL; ai[bb] = 0ULL; ah[bb] = 0ULL; }
        gemm3k(wi2, hb1, j, ar, az, ai);
        gemm3k(wh2, hb2, j, ar, az, ah);
        #pragma unroll
        for (int bb = 0; bb < RPT; ++bb) {
            float r  = sigf(hsum2(ar[bb]) + c2r);
            float u  = sigf(hsum2(az[bb]) + c2z);
            float n  = tanh_acc(fmaf(r, hsum2(ah[bb]) + c2h, hsum2(ai[bb]) + c2i));
            float ho = hb2[bb * HD + j];
            hnew[bb] = (1.0f - u) * n + u * ho;
        }
        __syncthreads();
        #pragma unroll
        for (int bb = 0; bb < RPT; ++bb) hb2[bb * HD + j] = hnew[bb];
        __syncthreads();

        // ================= logits + argmax (k-packed) =======================
        u64 acc[2] = {0ULL, 0ULL};
        const float* hk = hbuf + (2 * NB + rg * 2) * HD;
        #pragma unroll 4
        for (int k4 = 0; k4 < 64; ++k4) {
            ulonglong2 wv = ow2[k4 * 64 + vv];
            #pragma unroll
            for (int rr = 0; rr < 2; ++rr) {
                ulonglong2 xv = *reinterpret_cast<const ulonglong2*>(hk + rr * HD + k4 * 4);
                fma2(acc[rr], wv.x, xv.x);
                fma2(acc[rr], wv.y, xv.y);
            }
        }
        #pragma unroll
        for (int rr = 0; rr < 2; ++rr) {
            float lv  = hsum2(acc[rr]) + ob;
            int   row = rg * 2 + rr;
            slog[row * TV + vv] = lv;
            out[((size_t)(b0 + row) * TSTEPS + t) * TV + vv] = lv;
        }
        __syncthreads();
        if (tid < NB) {
            const float* lr = slog + tid * TV;
            float best = lr[0];
            int   bi   = 0;
            #pragma unroll 8
            for (int v2 = 1; v2 < TV; ++v2) {
                float lvv = lr[v2];
                if (lvv > best) { best = lvv; bi = v2; }   // first-max semantics
            }
            stok[tid] = bi;
        }
        __syncthreads();
    }
}

// ---------------- launch ------------------------------------------------------
extern "C" void kernel_launch(void* const* d_in, const int* in_sizes, int n_in,
                              void* d_out, int out_size)
{
    const float* z     = (const float*)d_in[0];
    const float* emb   = (const float*)d_in[1];
    const float* z2h_w = (const float*)d_in[2];
    const float* z2h_b = (const float*)d_in[3];
    const float* out_w = (const float*)d_in[4];
    const float* out_b = (const float*)d_in[5];
    const float* w_ih0 = (const float*)d_in[6];
    const float* w_hh0 = (const float*)d_in[7];
    const float* b_ih0 = (const float*)d_in[8];
    const float* b_hh0 = (const float*)d_in[9];
    const float* w_ih1 = (const float*)d_in[10];
    const float* w_hh1 = (const float*)d_in[11];
    const float* b_ih1 = (const float*)d_in[12];
    const float* b_hh1 = (const float*)d_in[13];
    const float* w_ih2 = (const float*)d_in[14];
    const float* w_hh2 = (const float*)d_in[15];
    const float* b_ih2 = (const float*)d_in[16];
    const float* b_hh2 = (const float*)d_in[17];

    prep_kernel<<<768, 256>>>(w_hh0, w_hh1, w_hh2, w_ih1, w_ih2,
                              out_w, emb, w_ih0, b_ih0);

    const int smem = (3 * NB * HD + NB * TV) * (int)sizeof(float) + NB * (int)sizeof(int);
    cudaFuncSetAttribute(decoder_kernel, cudaFuncAttributeMaxDynamicSharedMemorySize, smem);

    decoder_kernel<<<4096 / NB, NTH, smem>>>(z, z2h_w, z2h_b,
                                             b_hh0, b_ih1, b_hh1, b_ih2, b_hh2,
                                             out_b, (float*)d_out);
}